// round 1
// baseline (speedup 1.0000x reference)
#include <cuda_runtime.h>
#include <cstdint>

#define N_NODES   100000
#define N_EDGES   1600000
#define D         64
#define NEG_SLOPE 0.2f

// Scratch (allocation-free rule: __device__ globals)
__device__ float g_ex[N_EDGES];          // exp(leaky_relu(e)) per edge
__device__ float g_denom[N_NODES];       // segment sum of ex per dst node
__device__ float g_g[(size_t)N_NODES * D]; // feat @ W_neigh^T

// ---------------------------------------------------------------------------
// Kernel 0: zero the softmax denominator
// ---------------------------------------------------------------------------
__global__ void zero_denom_kernel() {
    int i = blockIdx.x * blockDim.x + threadIdx.x;
    if (i < N_NODES) g_denom[i] = 0.0f;
}

// ---------------------------------------------------------------------------
// Kernel 1: per-edge un-normalized softmax weight + denominator accumulation
//   e  = leaky_relu(rel[i,0]*a0 + rel[i,1]*a1)
//   ex = exp(e)   (max-subtraction skipped: e is bounded, cancels exactly)
// ---------------------------------------------------------------------------
__global__ void edge_pre_kernel(const float* __restrict__ rel,
                                const float* __restrict__ attn,
                                const int*   __restrict__ dst) {
    int i = blockIdx.x * blockDim.x + threadIdx.x;
    if (i >= N_EDGES) return;
    float a0 = __ldg(&attn[0]);
    float a1 = __ldg(&attn[1]);
    float2 r = reinterpret_cast<const float2*>(rel)[i];
    float e = r.x * a0 + r.y * a1;
    e = (e > 0.0f) ? e : NEG_SLOPE * e;
    float ex = __expf(e);
    g_ex[i] = ex;
    atomicAdd(&g_denom[dst[i]], ex);
}

// ---------------------------------------------------------------------------
// Kernel 2: fused dual GEMM.
//   out[n] = feat[n] @ W_self^T + (b_self + b_neigh)   (written to d_out)
//   g[n]   = feat[n] @ W_neigh^T                        (scratch)
// 64 nodes per block, 256 threads, 4 nodes x 4 outs per thread, weights
// transposed in shared memory. Exactly 48KB static smem.
// ---------------------------------------------------------------------------
__global__ __launch_bounds__(256) void fused_gemm_kernel(
    const float* __restrict__ feat,
    const float* __restrict__ Ws, const float* __restrict__ bs,
    const float* __restrict__ Wn, const float* __restrict__ bn,
    float* __restrict__ out) {
    __shared__ float sF [64][64];   // sF[node][k]
    __shared__ float sWs[64][64];   // sWs[k][o]  (transposed)
    __shared__ float sWn[64][64];   // sWn[k][o]  (transposed)

    const int tx = threadIdx.x;
    const int nodeBase = blockIdx.x * 64;

    // Load + transpose weights
    #pragma unroll 4
    for (int i = tx; i < 4096; i += 256) {
        int o = i >> 6, k = i & 63;
        sWs[k][o] = Ws[i];
        sWn[k][o] = Wn[i];
    }
    // Load feat tile (float4)
    #pragma unroll 4
    for (int i = tx; i < 1024; i += 256) {
        int n  = i >> 4;
        int c4 = i & 15;
        int node = nodeBase + n;
        float4 v = (node < N_NODES)
                       ? reinterpret_cast<const float4*>(feat)[(size_t)node * 16 + c4]
                       : make_float4(0.f, 0.f, 0.f, 0.f);
        reinterpret_cast<float4*>(&sF[n][0])[c4] = v;
    }
    __syncthreads();

    const int oc = (tx & 15) * 4;   // 4 consecutive output cols
    const int nr = tx >> 4;         // node rows nr, nr+16, nr+32, nr+48

    float accS[4][4] = {};
    float accN[4][4] = {};

    #pragma unroll 8
    for (int k = 0; k < 64; k++) {
        float4 ws = *reinterpret_cast<const float4*>(&sWs[k][oc]);
        float4 wn = *reinterpret_cast<const float4*>(&sWn[k][oc]);
        #pragma unroll
        for (int i = 0; i < 4; i++) {
            float f = sF[nr + 16 * i][k];
            accS[i][0] += f * ws.x; accS[i][1] += f * ws.y;
            accS[i][2] += f * ws.z; accS[i][3] += f * ws.w;
            accN[i][0] += f * wn.x; accN[i][1] += f * wn.y;
            accN[i][2] += f * wn.z; accN[i][3] += f * wn.w;
        }
    }

    // Bias (read straight from gmem: tiny, L1/L2-cached)
    float b0 = __ldg(&bs[oc])     + __ldg(&bn[oc]);
    float b1 = __ldg(&bs[oc + 1]) + __ldg(&bn[oc + 1]);
    float b2 = __ldg(&bs[oc + 2]) + __ldg(&bn[oc + 2]);
    float b3 = __ldg(&bs[oc + 3]) + __ldg(&bn[oc + 3]);

    #pragma unroll
    for (int i = 0; i < 4; i++) {
        int node = nodeBase + nr + 16 * i;
        if (node < N_NODES) {
            float4 o1 = make_float4(accS[i][0] + b0, accS[i][1] + b1,
                                    accS[i][2] + b2, accS[i][3] + b3);
            float4 o2 = make_float4(accN[i][0], accN[i][1],
                                    accN[i][2], accN[i][3]);
            reinterpret_cast<float4*>(out)[(size_t)node * 16 + (oc >> 2)] = o1;
            reinterpret_cast<float4*>(g_g)[(size_t)node * 16 + (oc >> 2)] = o2;
        }
    }
}

// ---------------------------------------------------------------------------
// Kernel 3: scatter-aggregate.  16 threads per edge, one float4 each.
//   d_out[dst] += (ex/denom[dst]) * g[src]
// ---------------------------------------------------------------------------
__global__ __launch_bounds__(256) void scatter_kernel(
    const int* __restrict__ src,
    const int* __restrict__ dst,
    float* __restrict__ out) {
    int tid = blockIdx.x * blockDim.x + threadIdx.x;
    int e = tid >> 4;
    if (e >= N_EDGES) return;
    int c = tid & 15;

    int s = __ldg(&src[e]);
    int d = __ldg(&dst[e]);
    float a = __ldg(&g_ex[e]) / __ldg(&g_denom[d]);

    float4 v = reinterpret_cast<const float4*>(g_g)[(size_t)s * 16 + c];
    float* p = out + (size_t)d * D + c * 4;
    asm volatile("red.global.add.v4.f32 [%0], {%1,%2,%3,%4};"
                 :: "l"(p), "f"(v.x * a), "f"(v.y * a),
                    "f"(v.z * a), "f"(v.w * a)
                 : "memory");
}

// ---------------------------------------------------------------------------
// Launch
// Inputs: 0 feat[100000,64] 1 rel[1.6M,2] 2 W_self[64,64] 3 b_self[64]
//         4 W_neigh[64,64]  5 b_neigh[64] 6 attn_e[2,1]   7 src[1.6M]
//         8 dst[1.6M];  output float32 [100000,64]
// ---------------------------------------------------------------------------
extern "C" void kernel_launch(void* const* d_in, const int* in_sizes, int n_in,
                              void* d_out, int out_size) {
    const float* feat = (const float*)d_in[0];
    const float* rel  = (const float*)d_in[1];
    const float* Ws   = (const float*)d_in[2];
    const float* bs   = (const float*)d_in[3];
    const float* Wn   = (const float*)d_in[4];
    const float* bn   = (const float*)d_in[5];
    const float* attn = (const float*)d_in[6];
    const int*   src  = (const int*)d_in[7];
    const int*   dst  = (const int*)d_in[8];
    float* out = (float*)d_out;

    zero_denom_kernel<<<(N_NODES + 255) / 256, 256>>>();
    edge_pre_kernel<<<(N_EDGES + 255) / 256, 256>>>(rel, attn, dst);
    fused_gemm_kernel<<<(N_NODES + 63) / 64, 256>>>(feat, Ws, bs, Wn, bn, out);
    scatter_kernel<<<(N_EDGES * 16 + 255) / 256, 256>>>(src, dst, out);
}

// round 2
// speedup vs baseline: 1.1496x; 1.1496x over previous
#include <cuda_runtime.h>
#include <cstdint>

#define N_NODES   100000
#define N_EDGES   1600000
#define D         64
#define NEG_SLOPE 0.2f
#define SCAN_B    1024
#define NB        ((N_NODES + SCAN_B - 1) / SCAN_B)   // 98

// Scratch (allocation-free rule: __device__ globals)
__device__ float  g_ex[N_EDGES];              // exp(leaky_relu(e)) per edge
__device__ int    g_cnt[N_NODES];             // in-degree histogram
__device__ int    g_off[N_NODES];             // exclusive CSR offsets
__device__ int    g_cur[N_NODES];             // placement cursors
__device__ int    g_bsum[NB];                 // per-block scan partials
__device__ float2 g_csr[N_EDGES];             // packed (src_bits, ex) CSR-ordered
__device__ float  g_g[(size_t)N_NODES * D];   // feat @ W_neigh^T

// ---------------------------------------------------------------------------
// K0: zero histogram
// ---------------------------------------------------------------------------
__global__ void zero_cnt_kernel() {
    int i = blockIdx.x * blockDim.x + threadIdx.x;
    if (i < N_NODES) g_cnt[i] = 0;
}

// ---------------------------------------------------------------------------
// K1: per-edge un-normalized softmax weight + dst histogram
//   (max-subtraction skipped: e bounded, cancels exactly in a = ex/denom)
// ---------------------------------------------------------------------------
__global__ void edge_pre_kernel(const float* __restrict__ rel,
                                const float* __restrict__ attn,
                                const int*   __restrict__ dst) {
    int i = blockIdx.x * blockDim.x + threadIdx.x;
    if (i >= N_EDGES) return;
    float a0 = __ldg(&attn[0]);
    float a1 = __ldg(&attn[1]);
    float2 r = reinterpret_cast<const float2*>(rel)[i];
    float e = r.x * a0 + r.y * a1;
    e = (e > 0.0f) ? e : NEG_SLOPE * e;
    g_ex[i] = __expf(e);
    atomicAdd(&g_cnt[dst[i]], 1);
}

// ---------------------------------------------------------------------------
// K2a: per-block exclusive scan of histogram (Hillis-Steele, 1024/block)
// ---------------------------------------------------------------------------
__global__ __launch_bounds__(SCAN_B) void scan1_kernel() {
    __shared__ int s[SCAN_B];
    int t = threadIdx.x;
    int i = blockIdx.x * SCAN_B + t;
    int v = (i < N_NODES) ? g_cnt[i] : 0;
    s[t] = v;
    __syncthreads();
    #pragma unroll
    for (int off = 1; off < SCAN_B; off <<= 1) {
        int x = (t >= off) ? s[t - off] : 0;
        __syncthreads();
        s[t] += x;
        __syncthreads();
    }
    if (i < N_NODES) g_off[i] = s[t] - v;          // exclusive within block
    if (t == SCAN_B - 1) g_bsum[blockIdx.x] = s[t]; // block total
}

// ---------------------------------------------------------------------------
// K2b: scan the 98 block totals (single block)
// ---------------------------------------------------------------------------
__global__ void scan2_kernel() {
    __shared__ int s[NB];
    int t = threadIdx.x;
    if (t < NB) s[t] = g_bsum[t];
    __syncthreads();
    if (t == 0) {
        int run = 0;
        for (int b = 0; b < NB; b++) { int c = s[b]; s[b] = run; run += c; }
    }
    __syncthreads();
    if (t < NB) g_bsum[t] = s[t];
}

// ---------------------------------------------------------------------------
// K2c: finalize offsets + init cursors
// ---------------------------------------------------------------------------
__global__ void scan3_kernel() {
    int i = blockIdx.x * blockDim.x + threadIdx.x;
    if (i >= N_NODES) return;
    int o = g_off[i] + g_bsum[i >> 10];
    g_off[i] = o;
    g_cur[i] = o;
}

// ---------------------------------------------------------------------------
// K3: bucket placement — pack (src, ex) into CSR order
// ---------------------------------------------------------------------------
__global__ void place_kernel(const int* __restrict__ src,
                             const int* __restrict__ dst) {
    int i = blockIdx.x * blockDim.x + threadIdx.x;
    if (i >= N_EDGES) return;
    int d = dst[i];
    int pos = atomicAdd(&g_cur[d], 1);
    g_csr[pos] = make_float2(__int_as_float(src[i]), g_ex[i]);
}

// ---------------------------------------------------------------------------
// K4: fused dual GEMM.
//   out[n] = feat[n] @ W_self^T + (b_self + b_neigh)
//   g[n]   = feat[n] @ W_neigh^T
// ---------------------------------------------------------------------------
__global__ __launch_bounds__(256) void fused_gemm_kernel(
    const float* __restrict__ feat,
    const float* __restrict__ Ws, const float* __restrict__ bs,
    const float* __restrict__ Wn, const float* __restrict__ bn,
    float* __restrict__ out) {
    __shared__ float sF [64][64];
    __shared__ float sWs[64][64];
    __shared__ float sWn[64][64];

    const int tx = threadIdx.x;
    const int nodeBase = blockIdx.x * 64;

    #pragma unroll 4
    for (int i = tx; i < 4096; i += 256) {
        int o = i >> 6, k = i & 63;
        sWs[k][o] = Ws[i];
        sWn[k][o] = Wn[i];
    }
    #pragma unroll 4
    for (int i = tx; i < 1024; i += 256) {
        int n  = i >> 4;
        int c4 = i & 15;
        int node = nodeBase + n;
        float4 v = (node < N_NODES)
                       ? reinterpret_cast<const float4*>(feat)[(size_t)node * 16 + c4]
                       : make_float4(0.f, 0.f, 0.f, 0.f);
        reinterpret_cast<float4*>(&sF[n][0])[c4] = v;
    }
    __syncthreads();

    const int oc = (tx & 15) * 4;
    const int nr = tx >> 4;

    float accS[4][4] = {};
    float accN[4][4] = {};

    #pragma unroll 8
    for (int k = 0; k < 64; k++) {
        float4 ws = *reinterpret_cast<const float4*>(&sWs[k][oc]);
        float4 wn = *reinterpret_cast<const float4*>(&sWn[k][oc]);
        #pragma unroll
        for (int i = 0; i < 4; i++) {
            float f = sF[nr + 16 * i][k];
            accS[i][0] += f * ws.x; accS[i][1] += f * ws.y;
            accS[i][2] += f * ws.z; accS[i][3] += f * ws.w;
            accN[i][0] += f * wn.x; accN[i][1] += f * wn.y;
            accN[i][2] += f * wn.z; accN[i][3] += f * wn.w;
        }
    }

    float b0 = __ldg(&bs[oc])     + __ldg(&bn[oc]);
    float b1 = __ldg(&bs[oc + 1]) + __ldg(&bn[oc + 1]);
    float b2 = __ldg(&bs[oc + 2]) + __ldg(&bn[oc + 2]);
    float b3 = __ldg(&bs[oc + 3]) + __ldg(&bn[oc + 3]);

    #pragma unroll
    for (int i = 0; i < 4; i++) {
        int node = nodeBase + nr + 16 * i;
        if (node < N_NODES) {
            float4 o1 = make_float4(accS[i][0] + b0, accS[i][1] + b1,
                                    accS[i][2] + b2, accS[i][3] + b3);
            float4 o2 = make_float4(accN[i][0], accN[i][1],
                                    accN[i][2], accN[i][3]);
            reinterpret_cast<float4*>(out)[(size_t)node * 16 + (oc >> 2)] = o1;
            reinterpret_cast<float4*>(g_g)[(size_t)node * 16 + (oc >> 2)] = o2;
        }
    }
}

// ---------------------------------------------------------------------------
// K5: gather-aggregate. One warp per dst node. No float atomics.
//   out[v] += (1/sum_e ex_e) * sum_e ex_e * g[src_e]
// ---------------------------------------------------------------------------
__global__ __launch_bounds__(256) void aggregate_kernel(float* __restrict__ out) {
    int warp = (blockIdx.x * blockDim.x + threadIdx.x) >> 5;
    if (warp >= N_NODES) return;
    const int lane = threadIdx.x & 31;

    const int beg = g_off[warp];
    const int cnt = g_cnt[warp];
    if (cnt == 0) return;

    float acc0 = 0.f, acc1 = 0.f, sum = 0.f;

    const int full = cnt & ~31;
    for (int base = 0; base < full; base += 32) {
        float2 p = __ldg(&g_csr[beg + base + lane]);
        #pragma unroll
        for (int j = 0; j < 32; j++) {
            float a = __shfl_sync(0xffffffffu, p.y, j);
            int   s = __shfl_sync(0xffffffffu, __float_as_int(p.x), j);
            sum  += a;
            acc0 += a * __ldg(&g_g[(size_t)s * D + lane]);
            acc1 += a * __ldg(&g_g[(size_t)s * D + 32 + lane]);
        }
    }
    const int rem = cnt - full;
    if (rem) {
        float2 p = (lane < rem) ? __ldg(&g_csr[beg + full + lane])
                                : make_float2(0.f, 0.f);
        for (int j = 0; j < rem; j++) {
            float a = __shfl_sync(0xffffffffu, p.y, j);
            int   s = __shfl_sync(0xffffffffu, __float_as_int(p.x), j);
            sum  += a;
            acc0 += a * __ldg(&g_g[(size_t)s * D + lane]);
            acc1 += a * __ldg(&g_g[(size_t)s * D + 32 + lane]);
        }
    }

    const float inv = 1.0f / sum;
    out[(size_t)warp * D + lane]      += acc0 * inv;
    out[(size_t)warp * D + 32 + lane] += acc1 * inv;
}

// ---------------------------------------------------------------------------
// Launch
// ---------------------------------------------------------------------------
extern "C" void kernel_launch(void* const* d_in, const int* in_sizes, int n_in,
                              void* d_out, int out_size) {
    const float* feat = (const float*)d_in[0];
    const float* rel  = (const float*)d_in[1];
    const float* Ws   = (const float*)d_in[2];
    const float* bs   = (const float*)d_in[3];
    const float* Wn   = (const float*)d_in[4];
    const float* bn   = (const float*)d_in[5];
    const float* attn = (const float*)d_in[6];
    const int*   src  = (const int*)d_in[7];
    const int*   dst  = (const int*)d_in[8];
    float* out = (float*)d_out;

    zero_cnt_kernel <<<(N_NODES + 255) / 256, 256>>>();
    edge_pre_kernel <<<(N_EDGES + 255) / 256, 256>>>(rel, attn, dst);
    scan1_kernel    <<<NB, SCAN_B>>>();
    scan2_kernel    <<<1, 128>>>();
    scan3_kernel    <<<(N_NODES + 255) / 256, 256>>>();
    place_kernel    <<<(N_EDGES + 255) / 256, 256>>>(src, dst);
    fused_gemm_kernel<<<(N_NODES + 63) / 64, 256>>>(feat, Ws, bs, Wn, bn, out);
    aggregate_kernel<<<(N_NODES * 32 + 255) / 256, 256>>>(out);
}

// round 3
// speedup vs baseline: 1.3233x; 1.1511x over previous
#include <cuda_runtime.h>
#include <cstdint>

#define N_NODES   100000
#define N_EDGES   1600000
#define D         64
#define NEG_SLOPE 0.2f
#define SCAN_B    1024
#define NB        ((N_NODES + SCAN_B - 1) / SCAN_B)   // 98

typedef unsigned long long ull;

// packed fp32x2 FMA (sm_103a FFMA2 — PTX-only pattern)
#define FMA2(d, a, b) \
    asm("fma.rn.f32x2 %0, %1, %2, %0;" : "+l"(d) : "l"(a), "l"(b))
#define UNPACK2(lo, hi, in) \
    asm("mov.b64 {%0, %1}, %2;" : "=f"(lo), "=f"(hi) : "l"(in))

// Scratch (allocation-free rule: __device__ globals)
__device__ int    g_cnt[N_NODES];             // in-degree histogram
__device__ int    g_off[N_NODES];             // exclusive CSR offsets
__device__ int    g_cur[N_NODES];             // placement cursors
__device__ int    g_bsum[NB];                 // per-block scan partials
__device__ float2 g_csr[N_EDGES];             // packed (src_bits, ex) CSR-ordered
__device__ float  g_g[(size_t)N_NODES * D];   // feat @ W_neigh^T

// ---------------------------------------------------------------------------
// K0: zero histogram
// ---------------------------------------------------------------------------
__global__ void zero_cnt_kernel() {
    int i = blockIdx.x * blockDim.x + threadIdx.x;
    if (i < N_NODES) g_cnt[i] = 0;
}

// ---------------------------------------------------------------------------
// K1: dst in-degree histogram
// ---------------------------------------------------------------------------
__global__ void hist_kernel(const int* __restrict__ dst) {
    int i = blockIdx.x * blockDim.x + threadIdx.x;
    if (i < N_EDGES) atomicAdd(&g_cnt[dst[i]], 1);
}

// ---------------------------------------------------------------------------
// K2a: per-block exclusive scan of histogram
// ---------------------------------------------------------------------------
__global__ __launch_bounds__(SCAN_B) void scan1_kernel() {
    __shared__ int s[SCAN_B];
    int t = threadIdx.x;
    int i = blockIdx.x * SCAN_B + t;
    int v = (i < N_NODES) ? g_cnt[i] : 0;
    s[t] = v;
    __syncthreads();
    #pragma unroll
    for (int off = 1; off < SCAN_B; off <<= 1) {
        int x = (t >= off) ? s[t - off] : 0;
        __syncthreads();
        s[t] += x;
        __syncthreads();
    }
    if (i < N_NODES) g_off[i] = s[t] - v;
    if (t == SCAN_B - 1) g_bsum[blockIdx.x] = s[t];
}

// ---------------------------------------------------------------------------
// K2b: fused block-prefix + finalize offsets + init cursors
//   Each block computes its own prefix over g_bsum with one warp reduction.
// ---------------------------------------------------------------------------
__global__ __launch_bounds__(SCAN_B) void scan2_kernel() {
    __shared__ int s_pref;
    int t = threadIdx.x, b = blockIdx.x;
    if (t < 32) {
        int acc = 0;
        for (int j = t; j < b; j += 32) acc += g_bsum[j];
        #pragma unroll
        for (int o = 16; o; o >>= 1) acc += __shfl_down_sync(0xffffffffu, acc, o);
        if (t == 0) s_pref = acc;
    }
    __syncthreads();
    int i = b * SCAN_B + t;
    if (i < N_NODES) {
        int o = g_off[i] + s_pref;
        g_off[i] = o;
        g_cur[i] = o;
    }
}

// ---------------------------------------------------------------------------
// K3: bucket placement with fused softmax weight.
//   ex = exp(leaky_relu(rel . attn))  (max-subtraction cancels exactly)
// ---------------------------------------------------------------------------
__global__ void place_kernel(const float* __restrict__ rel,
                             const float* __restrict__ attn,
                             const int*   __restrict__ src,
                             const int*   __restrict__ dst) {
    int i = blockIdx.x * blockDim.x + threadIdx.x;
    if (i >= N_EDGES) return;
    float a0 = __ldg(&attn[0]);
    float a1 = __ldg(&attn[1]);
    float2 r = reinterpret_cast<const float2*>(rel)[i];
    float e = r.x * a0 + r.y * a1;
    e = (e > 0.0f) ? e : NEG_SLOPE * e;
    float ex = __expf(e);
    int d = dst[i];
    int pos = atomicAdd(&g_cur[d], 1);
    g_csr[pos] = make_float2(__int_as_float(src[i]), ex);
}

// ---------------------------------------------------------------------------
// K4: fused dual GEMM with packed f32x2 FMA.
//   out[n] = feat[n] @ W_self^T + (b_self + b_neigh)
//   g[n]   = feat[n] @ W_neigh^T
// 128 threads, 64-node tile. Thread = 4 cols (2 col-pairs) x 8 nodes.
// Feat tile stored DUPLICATED (v,v) so the f32x2 "a" operand is one LDS.64.
// Weight col-pairs come out of an LDS.128 as aligned 64-bit halves.
// smem: sF2[64][130] (pad kills store conflicts) + 2 weight tiles = 66048 B.
// ---------------------------------------------------------------------------
#define GEMM_SMEM_BYTES (64 * 130 * 4 + 2 * 64 * 64 * 4)

__global__ __launch_bounds__(128) void fused_gemm_kernel(
    const float* __restrict__ feat,
    const float* __restrict__ Ws, const float* __restrict__ bs,
    const float* __restrict__ Wn, const float* __restrict__ bn,
    float* __restrict__ out) {
    extern __shared__ float smem[];
    float (*sF2)[130] = (float(*)[130])smem;                  // dup feat: [k][2n+h]
    float (*sWs)[64]  = (float(*)[64])(smem + 64 * 130);      // transposed: [k][o]
    float (*sWn)[64]  = (float(*)[64])(smem + 64 * 130 + 4096);

    const int t = threadIdx.x;
    const int nodeBase = blockIdx.x * 64;

    // Weights: global row-major [o][k], store transposed with XOR swizzle at
    // float4 granularity (physical group = (g + (k&15)) & 15) -> store is
    // 2-way instead of 32-way conflicted, loads stay contiguous/aligned.
    for (int i = t; i < 4096; i += 128) {
        int o = i >> 6, k = i & 63;
        int col = (o & 3) | ((((o >> 2) + (k & 15)) & 15) << 2);
        sWs[k][col] = Ws[i];
        sWn[k][col] = Wn[i];
    }
    // Feat: global [n][k] coalesced read, duplicated (v,v) transposed store.
    for (int i = t; i < 4096; i += 128) {
        int n = i >> 6, k = i & 63;
        int node = nodeBase + n;
        float v = (node < N_NODES) ? __ldg(&feat[(size_t)node * D + k]) : 0.f;
        *reinterpret_cast<float2*>(&sF2[k][n * 2]) = make_float2(v, v);
    }
    __syncthreads();

    const int oc = (t & 15) * 4;    // 4 output cols = 2 col-pairs
    const int nr = t >> 4;          // 8 nodes: nr*8 .. nr*8+7

    ull accS[8][2] = {};
    ull accN[8][2] = {};

    #pragma unroll 8
    for (int k = 0; k < 64; k++) {
        const int g4 = (((oc >> 2) + (k & 15)) & 15) << 2;
        ulonglong2 ws = *reinterpret_cast<const ulonglong2*>(&sWs[k][g4]);
        ulonglong2 wn = *reinterpret_cast<const ulonglong2*>(&sWn[k][g4]);
        const float* frow = &sF2[k][nr * 16];
        #pragma unroll
        for (int j = 0; j < 8; j++) {
            ull f = *reinterpret_cast<const ull*>(frow + j * 2);
            FMA2(accS[j][0], f, ws.x);
            FMA2(accS[j][1], f, ws.y);
            FMA2(accN[j][0], f, wn.x);
            FMA2(accN[j][1], f, wn.y);
        }
    }

    float b0 = __ldg(&bs[oc])     + __ldg(&bn[oc]);
    float b1 = __ldg(&bs[oc + 1]) + __ldg(&bn[oc + 1]);
    float b2 = __ldg(&bs[oc + 2]) + __ldg(&bn[oc + 2]);
    float b3 = __ldg(&bs[oc + 3]) + __ldg(&bn[oc + 3]);

    #pragma unroll
    for (int j = 0; j < 8; j++) {
        int node = nodeBase + nr * 8 + j;
        if (node < N_NODES) {
            float s0, s1, s2, s3, n0, n1, n2, n3;
            UNPACK2(s0, s1, accS[j][0]);
            UNPACK2(s2, s3, accS[j][1]);
            UNPACK2(n0, n1, accN[j][0]);
            UNPACK2(n2, n3, accN[j][1]);
            reinterpret_cast<float4*>(out)[(size_t)node * 16 + (oc >> 2)] =
                make_float4(s0 + b0, s1 + b1, s2 + b2, s3 + b3);
            reinterpret_cast<float4*>(g_g)[(size_t)node * 16 + (oc >> 2)] =
                make_float4(n0, n1, n2, n3);
        }
    }
}

// ---------------------------------------------------------------------------
// K5: gather-aggregate. One warp per dst node, broadcast CSR loads (no SHFL).
//   out[v] += (1/sum ex) * sum ex * g[src]
// ---------------------------------------------------------------------------
__global__ __launch_bounds__(256) void aggregate_kernel(float* __restrict__ out) {
    int warp = (blockIdx.x * blockDim.x + threadIdx.x) >> 5;
    if (warp >= N_NODES) return;
    const int lane = threadIdx.x & 31;

    const int beg = g_off[warp];
    const int cnt = g_cnt[warp];
    if (cnt == 0) return;

    float acc0a = 0.f, acc1a = 0.f, suma = 0.f;
    float acc0b = 0.f, acc1b = 0.f, sumb = 0.f;

    int j = 0;
    for (; j + 2 <= cnt; j += 2) {
        float2 p0 = __ldg(&g_csr[beg + j]);       // uniform addr: broadcast
        float2 p1 = __ldg(&g_csr[beg + j + 1]);
        int s0 = __float_as_int(p0.x);
        int s1 = __float_as_int(p1.x);
        float v00 = __ldg(&g_g[(size_t)s0 * D + lane]);
        float v01 = __ldg(&g_g[(size_t)s0 * D + 32 + lane]);
        float v10 = __ldg(&g_g[(size_t)s1 * D + lane]);
        float v11 = __ldg(&g_g[(size_t)s1 * D + 32 + lane]);
        suma += p0.y;  acc0a += p0.y * v00;  acc1a += p0.y * v01;
        sumb += p1.y;  acc0b += p1.y * v10;  acc1b += p1.y * v11;
    }
    if (j < cnt) {
        float2 p = __ldg(&g_csr[beg + j]);
        int s = __float_as_int(p.x);
        suma  += p.y;
        acc0a += p.y * __ldg(&g_g[(size_t)s * D + lane]);
        acc1a += p.y * __ldg(&g_g[(size_t)s * D + 32 + lane]);
    }

    const float inv = 1.0f / (suma + sumb);
    out[(size_t)warp * D + lane]      += (acc0a + acc0b) * inv;
    out[(size_t)warp * D + 32 + lane] += (acc1a + acc1b) * inv;
}

// ---------------------------------------------------------------------------
// Launch
// ---------------------------------------------------------------------------
extern "C" void kernel_launch(void* const* d_in, const int* in_sizes, int n_in,
                              void* d_out, int out_size) {
    const float* feat = (const float*)d_in[0];
    const float* rel  = (const float*)d_in[1];
    const float* Ws   = (const float*)d_in[2];
    const float* bs   = (const float*)d_in[3];
    const float* Wn   = (const float*)d_in[4];
    const float* bn   = (const float*)d_in[5];
    const float* attn = (const float*)d_in[6];
    const int*   src  = (const int*)d_in[7];
    const int*   dst  = (const int*)d_in[8];
    float* out = (float*)d_out;

    static bool attr_set = false;
    if (!attr_set) {
        cudaFuncSetAttribute(fused_gemm_kernel,
                             cudaFuncAttributeMaxDynamicSharedMemorySize,
                             GEMM_SMEM_BYTES);
        attr_set = true;
    }

    zero_cnt_kernel <<<(N_NODES + 255) / 256, 256>>>();
    hist_kernel     <<<(N_EDGES + 255) / 256, 256>>>(dst);
    scan1_kernel    <<<NB, SCAN_B>>>();
    scan2_kernel    <<<NB, SCAN_B>>>();
    place_kernel    <<<(N_EDGES + 255) / 256, 256>>>(rel, attn, src, dst);
    fused_gemm_kernel<<<(N_NODES + 63) / 64, 128, GEMM_SMEM_BYTES>>>(
        feat, Ws, bs, Wn, bn, out);
    aggregate_kernel<<<(N_NODES * 32 + 255) / 256, 256>>>(out);
}

// round 5
// speedup vs baseline: 1.4318x; 1.0820x over previous
#include <cuda_runtime.h>
#include <cuda_fp16.h>
#include <cstdint>

#define N_NODES   100000
#define N_EDGES   1600000
#define D         64
#define NEG_SLOPE 0.2f
#define SCAN_B    1024
#define NB        ((N_NODES + SCAN_B - 1) / SCAN_B)   // 98

typedef unsigned long long ull;

// packed fp32x2 FMA (sm_103a FFMA2 — PTX-only pattern)
#define FMA2(d, a, b) \
    asm("fma.rn.f32x2 %0, %1, %2, %0;" : "+l"(d) : "l"(a), "l"(b))
#define UNPACK2(lo, hi, in) \
    asm("mov.b64 {%0, %1}, %2;" : "=f"(lo), "=f"(hi) : "l"(in))

__device__ __forceinline__ uint32_t h2_bits(__half2 h) {
    uint32_t u;
    memcpy(&u, &h, 4);
    return u;
}

// Scratch (allocation-free rule: __device__ globals)
__device__ int     g_cnt[N_NODES];              // in-degree histogram
__device__ int     g_off[N_NODES];              // exclusive CSR offsets
__device__ int     g_cur[N_NODES];              // placement cursors
__device__ int     g_bsum[NB];                  // per-block scan partials
__device__ float2  g_csr[N_EDGES];              // packed (src_bits, ex)
__device__ __half2 g_gh[(size_t)N_NODES * 32];  // feat @ W_neigh^T  (fp16)

// ---------------------------------------------------------------------------
// K1: dst in-degree histogram
// ---------------------------------------------------------------------------
__global__ void hist_kernel(const int* __restrict__ dst) {
    int i = blockIdx.x * blockDim.x + threadIdx.x;
    if (i < N_EDGES) atomicAdd(&g_cnt[dst[i]], 1);
}

// ---------------------------------------------------------------------------
// K2a: per-block exclusive scan (warp-shuffle based, 2 barriers)
// ---------------------------------------------------------------------------
__global__ __launch_bounds__(SCAN_B) void scan1_kernel() {
    __shared__ int wsum[32];
    const int t = threadIdx.x;
    const int lane = t & 31, w = t >> 5;
    const int i = blockIdx.x * SCAN_B + t;
    int v = (i < N_NODES) ? g_cnt[i] : 0;

    int x = v;
    #pragma unroll
    for (int o = 1; o < 32; o <<= 1) {
        int y = __shfl_up_sync(0xffffffffu, x, o);
        if (lane >= o) x += y;
    }
    if (lane == 31) wsum[w] = x;
    __syncthreads();
    if (w == 0) {
        int s = wsum[lane];
        #pragma unroll
        for (int o = 1; o < 32; o <<= 1) {
            int y = __shfl_up_sync(0xffffffffu, s, o);
            if (lane >= o) s += y;
        }
        wsum[lane] = s;
    }
    __syncthreads();
    int incl = x + (w ? wsum[w - 1] : 0);
    if (i < N_NODES) g_off[i] = incl - v;
    if (t == SCAN_B - 1) g_bsum[blockIdx.x] = incl;
}

// ---------------------------------------------------------------------------
// K2b: fused block-prefix + finalize offsets + init cursors
// ---------------------------------------------------------------------------
__global__ __launch_bounds__(SCAN_B) void scan2_kernel() {
    __shared__ int s_pref;
    int t = threadIdx.x, b = blockIdx.x;
    if (t < 32) {
        int acc = 0;
        for (int j = t; j < b; j += 32) acc += g_bsum[j];
        #pragma unroll
        for (int o = 16; o; o >>= 1) acc += __shfl_down_sync(0xffffffffu, acc, o);
        if (t == 0) s_pref = acc;
    }
    __syncthreads();
    int i = b * SCAN_B + t;
    if (i < N_NODES) {
        int o = g_off[i] + s_pref;
        g_off[i] = o;
        g_cur[i] = o;
    }
}

// ---------------------------------------------------------------------------
// K3: bucket placement with fused softmax weight.
//   ex = exp(leaky_relu(rel . attn))  (max-subtraction cancels exactly)
// ---------------------------------------------------------------------------
__global__ void place_kernel(const float* __restrict__ rel,
                             const float* __restrict__ attn,
                             const int*   __restrict__ src,
                             const int*   __restrict__ dst) {
    int i = blockIdx.x * blockDim.x + threadIdx.x;
    if (i >= N_EDGES) return;
    float a0 = __ldg(&attn[0]);
    float a1 = __ldg(&attn[1]);
    float2 r = reinterpret_cast<const float2*>(rel)[i];
    float e = r.x * a0 + r.y * a1;
    e = (e > 0.0f) ? e : NEG_SLOPE * e;
    float ex = __expf(e);
    int d = dst[i];
    int pos = atomicAdd(&g_cur[d], 1);
    g_csr[pos] = make_float2(__int_as_float(src[i]), ex);
}

// ---------------------------------------------------------------------------
// K4: fused dual GEMM with packed f32x2 FMA.
//   out[n]  = feat[n] @ W_self^T + (b_self + b_neigh)    (fp32)
//   g_gh[n] = feat[n] @ W_neigh^T                        (fp16)
// ---------------------------------------------------------------------------
#define GEMM_SMEM_BYTES (64 * 130 * 4 + 2 * 64 * 64 * 4)

__global__ __launch_bounds__(128) void fused_gemm_kernel(
    const float* __restrict__ feat,
    const float* __restrict__ Ws, const float* __restrict__ bs,
    const float* __restrict__ Wn, const float* __restrict__ bn,
    float* __restrict__ out) {
    extern __shared__ float smem[];
    float (*sF2)[130] = (float(*)[130])smem;                  // dup feat [k][2n+h]
    float (*sWs)[64]  = (float(*)[64])(smem + 64 * 130);      // transposed [k][o]
    float (*sWn)[64]  = (float(*)[64])(smem + 64 * 130 + 4096);

    const int t = threadIdx.x;
    const int nodeBase = blockIdx.x * 64;

    // Weights: transpose-store with XOR swizzle at float4 granularity.
    for (int i = t; i < 4096; i += 128) {
        int o = i >> 6, k = i & 63;
        int col = (o & 3) | ((((o >> 2) + (k & 15)) & 15) << 2);
        sWs[k][col] = Ws[i];
        sWn[k][col] = Wn[i];
    }
    // Feat: coalesced read, duplicated (v,v) transposed store.
    for (int i = t; i < 4096; i += 128) {
        int n = i >> 6, k = i & 63;
        int node = nodeBase + n;
        float v = (node < N_NODES) ? __ldg(&feat[(size_t)node * D + k]) : 0.f;
        *reinterpret_cast<float2*>(&sF2[k][n * 2]) = make_float2(v, v);
    }
    __syncthreads();

    const int oc = (t & 15) * 4;    // 4 output cols = 2 col-pairs
    const int nr = t >> 4;          // 8 nodes: nr*8 .. nr*8+7

    ull accS[8][2] = {};
    ull accN[8][2] = {};

    #pragma unroll 8
    for (int k = 0; k < 64; k++) {
        const int g4 = (((oc >> 2) + (k & 15)) & 15) << 2;
        ulonglong2 ws = *reinterpret_cast<const ulonglong2*>(&sWs[k][g4]);
        ulonglong2 wn = *reinterpret_cast<const ulonglong2*>(&sWn[k][g4]);
        const float* frow = &sF2[k][nr * 16];
        #pragma unroll
        for (int j = 0; j < 8; j++) {
            ull f = *reinterpret_cast<const ull*>(frow + j * 2);
            FMA2(accS[j][0], f, ws.x);
            FMA2(accS[j][1], f, ws.y);
            FMA2(accN[j][0], f, wn.x);
            FMA2(accN[j][1], f, wn.y);
        }
    }

    float b0 = __ldg(&bs[oc])     + __ldg(&bn[oc]);
    float b1 = __ldg(&bs[oc + 1]) + __ldg(&bn[oc + 1]);
    float b2 = __ldg(&bs[oc + 2]) + __ldg(&bn[oc + 2]);
    float b3 = __ldg(&bs[oc + 3]) + __ldg(&bn[oc + 3]);

    #pragma unroll
    for (int j = 0; j < 8; j++) {
        int node = nodeBase + nr * 8 + j;
        if (node < N_NODES) {
            float s0, s1, s2, s3, n0, n1, n2, n3;
            UNPACK2(s0, s1, accS[j][0]);
            UNPACK2(s2, s3, accS[j][1]);
            UNPACK2(n0, n1, accN[j][0]);
            UNPACK2(n2, n3, accN[j][1]);
            reinterpret_cast<float4*>(out)[(size_t)node * 16 + (oc >> 2)] =
                make_float4(s0 + b0, s1 + b1, s2 + b2, s3 + b3);
            // fp16 neighbor features, two half2 packed into one 8B store
            __half2 h01 = __floats2half2_rn(n0, n1);
            __half2 h23 = __floats2half2_rn(n2, n3);
            *reinterpret_cast<uint2*>(&g_gh[(size_t)node * 32 + (oc >> 1)]) =
                make_uint2(h2_bits(h01), h2_bits(h23));
        }
    }
}

// ---------------------------------------------------------------------------
// K5: gather-aggregate. One warp per dst node; fp16 rows = 1 line/edge.
//   out[v] += (1/sum ex) * sum ex * g[src]
// ---------------------------------------------------------------------------
__global__ __launch_bounds__(256) void aggregate_kernel(float* __restrict__ out) {
    int warp = (blockIdx.x * blockDim.x + threadIdx.x) >> 5;
    if (warp >= N_NODES) return;
    const int lane = threadIdx.x & 31;

    const int beg = g_off[warp];
    const int cnt = g_cnt[warp];
    if (cnt == 0) return;

    float ax = 0.f, ay = 0.f, sum = 0.f;

    int j = 0;
    for (; j + 4 <= cnt; j += 4) {
        float2 p0 = __ldg(&g_csr[beg + j]);       // uniform addr: broadcast
        float2 p1 = __ldg(&g_csr[beg + j + 1]);
        float2 p2 = __ldg(&g_csr[beg + j + 2]);
        float2 p3 = __ldg(&g_csr[beg + j + 3]);
        __half2 h0 = __ldg(&g_gh[(size_t)__float_as_int(p0.x) * 32 + lane]);
        __half2 h1 = __ldg(&g_gh[(size_t)__float_as_int(p1.x) * 32 + lane]);
        __half2 h2 = __ldg(&g_gh[(size_t)__float_as_int(p2.x) * 32 + lane]);
        __half2 h3 = __ldg(&g_gh[(size_t)__float_as_int(p3.x) * 32 + lane]);
        float2 f0 = __half22float2(h0);
        float2 f1 = __half22float2(h1);
        float2 f2 = __half22float2(h2);
        float2 f3 = __half22float2(h3);
        sum += p0.y + p1.y + p2.y + p3.y;
        ax += p0.y * f0.x + p1.y * f1.x + p2.y * f2.x + p3.y * f3.x;
        ay += p0.y * f0.y + p1.y * f1.y + p2.y * f2.y + p3.y * f3.y;
    }
    for (; j < cnt; j++) {
        float2 p = __ldg(&g_csr[beg + j]);
        float2 f = __half22float2(
            __ldg(&g_gh[(size_t)__float_as_int(p.x) * 32 + lane]));
        sum += p.y;
        ax  += p.y * f.x;
        ay  += p.y * f.y;
    }

    const float inv = 1.0f / sum;
    float2* po = reinterpret_cast<float2*>(out) + (size_t)warp * 32 + lane;
    float2 cur = *po;
    cur.x += ax * inv;
    cur.y += ay * inv;
    *po = cur;
}

// ---------------------------------------------------------------------------
// Launch
// ---------------------------------------------------------------------------
extern "C" void kernel_launch(void* const* d_in, const int* in_sizes, int n_in,
                              void* d_out, int out_size) {
    const float* feat = (const float*)d_in[0];
    const float* rel  = (const float*)d_in[1];
    const float* Ws   = (const float*)d_in[2];
    const float* bs   = (const float*)d_in[3];
    const float* Wn   = (const float*)d_in[4];
    const float* bn   = (const float*)d_in[5];
    const float* attn = (const float*)d_in[6];
    const int*   src  = (const int*)d_in[7];
    const int*   dst  = (const int*)d_in[8];
    float* out = (float*)d_out;

    static void* cnt_addr = nullptr;
    if (!cnt_addr) {
        cudaFuncSetAttribute(fused_gemm_kernel,
                             cudaFuncAttributeMaxDynamicSharedMemorySize,
                             GEMM_SMEM_BYTES);
        cudaGetSymbolAddress(&cnt_addr, g_cnt);
    }

    cudaMemsetAsync(cnt_addr, 0, N_NODES * sizeof(int));
    hist_kernel     <<<(N_EDGES + 255) / 256, 256>>>(dst);
    scan1_kernel    <<<NB, SCAN_B>>>();
    scan2_kernel    <<<NB, SCAN_B>>>();
    place_kernel    <<<(N_EDGES + 255) / 256, 256>>>(rel, attn, src, dst);
    fused_gemm_kernel<<<(N_NODES + 63) / 64, 128, GEMM_SMEM_BYTES>>>(
        feat, Ws, bs, Wn, bn, out);
    aggregate_kernel<<<(N_NODES * 32 + 255) / 256, 256>>>(out);
}

// round 6
// speedup vs baseline: 1.5462x; 1.0799x over previous
#include <cuda_runtime.h>
#include <cuda_fp16.h>
#include <cstdint>

#define N_NODES   100000
#define N_EDGES   1600000
#define D         64
#define NEG_SLOPE 0.2f
#define SCAN_B    1024
#define NB        ((N_NODES + SCAN_B - 1) / SCAN_B)   // 98

typedef unsigned long long ull;

// packed fp32x2 FMA (sm_103a FFMA2 — PTX-only pattern)
#define FMA2(d, a, b) \
    asm("fma.rn.f32x2 %0, %1, %2, %0;" : "+l"(d) : "l"(a), "l"(b))
#define UNPACK2(lo, hi, in) \
    asm("mov.b64 {%0, %1}, %2;" : "=f"(lo), "=f"(hi) : "l"(in))

__device__ __forceinline__ uint32_t h2_bits(__half2 h) {
    uint32_t u;
    memcpy(&u, &h, 4);
    return u;
}

// Scratch (allocation-free rule: __device__ globals)
__device__ int     g_cnt[N_NODES];              // in-degree histogram
__device__ int     g_off[N_NODES];              // exclusive CSR offsets
__device__ int     g_cur[N_NODES];              // placement cursors
__device__ int     g_bsum[NB];                  // per-block scan partials
__device__ float2  g_csr[N_EDGES];              // packed (src_bits, ex)
__device__ __half2 g_gh[(size_t)N_NODES * 32];  // feat @ W_neigh^T  (fp16)

// ---------------------------------------------------------------------------
// K1: dst in-degree histogram
// ---------------------------------------------------------------------------
__global__ void hist_kernel(const int* __restrict__ dst) {
    int i = blockIdx.x * blockDim.x + threadIdx.x;
    if (i < N_EDGES) atomicAdd(&g_cnt[dst[i]], 1);
}

// ---------------------------------------------------------------------------
// K2a: per-block exclusive scan (warp-shuffle based, 2 barriers)
// ---------------------------------------------------------------------------
__global__ __launch_bounds__(SCAN_B) void scan1_kernel() {
    __shared__ int wsum[32];
    const int t = threadIdx.x;
    const int lane = t & 31, w = t >> 5;
    const int i = blockIdx.x * SCAN_B + t;
    int v = (i < N_NODES) ? g_cnt[i] : 0;

    int x = v;
    #pragma unroll
    for (int o = 1; o < 32; o <<= 1) {
        int y = __shfl_up_sync(0xffffffffu, x, o);
        if (lane >= o) x += y;
    }
    if (lane == 31) wsum[w] = x;
    __syncthreads();
    if (w == 0) {
        int s = wsum[lane];
        #pragma unroll
        for (int o = 1; o < 32; o <<= 1) {
            int y = __shfl_up_sync(0xffffffffu, s, o);
            if (lane >= o) s += y;
        }
        wsum[lane] = s;
    }
    __syncthreads();
    int incl = x + (w ? wsum[w - 1] : 0);
    if (i < N_NODES) g_off[i] = incl - v;
    if (t == SCAN_B - 1) g_bsum[blockIdx.x] = incl;
}

// ---------------------------------------------------------------------------
// K2b: fused block-prefix + finalize offsets + init cursors
// ---------------------------------------------------------------------------
__global__ __launch_bounds__(SCAN_B) void scan2_kernel() {
    __shared__ int s_pref;
    int t = threadIdx.x, b = blockIdx.x;
    if (t < 32) {
        int acc = 0;
        for (int j = t; j < b; j += 32) acc += g_bsum[j];
        #pragma unroll
        for (int o = 16; o; o >>= 1) acc += __shfl_down_sync(0xffffffffu, acc, o);
        if (t == 0) s_pref = acc;
    }
    __syncthreads();
    int i = b * SCAN_B + t;
    if (i < N_NODES) {
        int o = g_off[i] + s_pref;
        g_off[i] = o;
        g_cur[i] = o;
    }
}

// ---------------------------------------------------------------------------
// K3: bucket placement with fused softmax weight.
//   ex = exp(leaky_relu(rel . attn))  (max-subtraction cancels exactly)
// ---------------------------------------------------------------------------
__global__ void place_kernel(const float* __restrict__ rel,
                             const float* __restrict__ attn,
                             const int*   __restrict__ src,
                             const int*   __restrict__ dst) {
    int i = blockIdx.x * blockDim.x + threadIdx.x;
    if (i >= N_EDGES) return;
    float a0 = __ldg(&attn[0]);
    float a1 = __ldg(&attn[1]);
    float2 r = reinterpret_cast<const float2*>(rel)[i];
    float e = r.x * a0 + r.y * a1;
    e = (e > 0.0f) ? e : NEG_SLOPE * e;
    float ex = __expf(e);
    int d = dst[i];
    int pos = atomicAdd(&g_cur[d], 1);
    g_csr[pos] = make_float2(__int_as_float(src[i]), ex);
}

// ---------------------------------------------------------------------------
// K4: fused dual GEMM with packed f32x2 FMA.  (runs on side stream, overlapped)
//   out[n]  = feat[n] @ W_self^T + (b_self + b_neigh)    (fp32)
//   g_gh[n] = feat[n] @ W_neigh^T                        (fp16)
// ---------------------------------------------------------------------------
#define GEMM_SMEM_BYTES (64 * 130 * 4 + 2 * 64 * 64 * 4)

__global__ __launch_bounds__(128) void fused_gemm_kernel(
    const float* __restrict__ feat,
    const float* __restrict__ Ws, const float* __restrict__ bs,
    const float* __restrict__ Wn, const float* __restrict__ bn,
    float* __restrict__ out) {
    extern __shared__ float smem[];
    float (*sF2)[130] = (float(*)[130])smem;                  // dup feat [k][2n+h]
    float (*sWs)[64]  = (float(*)[64])(smem + 64 * 130);      // transposed [k][o]
    float (*sWn)[64]  = (float(*)[64])(smem + 64 * 130 + 4096);

    const int t = threadIdx.x;
    const int nodeBase = blockIdx.x * 64;

    // Weights: transpose-store with XOR swizzle at float4 granularity.
    for (int i = t; i < 4096; i += 128) {
        int o = i >> 6, k = i & 63;
        int col = (o & 3) | ((((o >> 2) + (k & 15)) & 15) << 2);
        sWs[k][col] = Ws[i];
        sWn[k][col] = Wn[i];
    }
    // Feat: coalesced read, duplicated (v,v) transposed store.
    for (int i = t; i < 4096; i += 128) {
        int n = i >> 6, k = i & 63;
        int node = nodeBase + n;
        float v = (node < N_NODES) ? __ldg(&feat[(size_t)node * D + k]) : 0.f;
        *reinterpret_cast<float2*>(&sF2[k][n * 2]) = make_float2(v, v);
    }
    __syncthreads();

    const int oc = (t & 15) * 4;    // 4 output cols = 2 col-pairs
    const int nr = t >> 4;          // 8 nodes: nr*8 .. nr*8+7

    ull accS[8][2] = {};
    ull accN[8][2] = {};

    #pragma unroll 8
    for (int k = 0; k < 64; k++) {
        const int g4 = (((oc >> 2) + (k & 15)) & 15) << 2;
        ulonglong2 ws = *reinterpret_cast<const ulonglong2*>(&sWs[k][g4]);
        ulonglong2 wn = *reinterpret_cast<const ulonglong2*>(&sWn[k][g4]);
        const float* frow = &sF2[k][nr * 16];
        #pragma unroll
        for (int j = 0; j < 8; j++) {
            ull f = *reinterpret_cast<const ull*>(frow + j * 2);
            FMA2(accS[j][0], f, ws.x);
            FMA2(accS[j][1], f, ws.y);
            FMA2(accN[j][0], f, wn.x);
            FMA2(accN[j][1], f, wn.y);
        }
    }

    float b0 = __ldg(&bs[oc])     + __ldg(&bn[oc]);
    float b1 = __ldg(&bs[oc + 1]) + __ldg(&bn[oc + 1]);
    float b2 = __ldg(&bs[oc + 2]) + __ldg(&bn[oc + 2]);
    float b3 = __ldg(&bs[oc + 3]) + __ldg(&bn[oc + 3]);

    #pragma unroll
    for (int j = 0; j < 8; j++) {
        int node = nodeBase + nr * 8 + j;
        if (node < N_NODES) {
            float s0, s1, s2, s3, n0, n1, n2, n3;
            UNPACK2(s0, s1, accS[j][0]);
            UNPACK2(s2, s3, accS[j][1]);
            UNPACK2(n0, n1, accN[j][0]);
            UNPACK2(n2, n3, accN[j][1]);
            reinterpret_cast<float4*>(out)[(size_t)node * 16 + (oc >> 2)] =
                make_float4(s0 + b0, s1 + b1, s2 + b2, s3 + b3);
            __half2 h01 = __floats2half2_rn(n0, n1);
            __half2 h23 = __floats2half2_rn(n2, n3);
            *reinterpret_cast<uint2*>(&g_gh[(size_t)node * 32 + (oc >> 1)]) =
                make_uint2(h2_bits(h01), h2_bits(h23));
        }
    }
}

// ---------------------------------------------------------------------------
// K5: gather-aggregate. One warp per dst node; fp16 rows = 1 line/edge.
//   out[v] += (1/sum ex) * sum ex * g[src]
// ---------------------------------------------------------------------------
__global__ __launch_bounds__(256) void aggregate_kernel(float* __restrict__ out) {
    int warp = (blockIdx.x * blockDim.x + threadIdx.x) >> 5;
    if (warp >= N_NODES) return;
    const int lane = threadIdx.x & 31;

    const int beg = g_off[warp];
    const int cnt = g_cnt[warp];
    if (cnt == 0) return;

    float ax = 0.f, ay = 0.f, sum = 0.f;

    int j = 0;
    for (; j + 4 <= cnt; j += 4) {
        float2 p0 = __ldg(&g_csr[beg + j]);       // uniform addr: broadcast
        float2 p1 = __ldg(&g_csr[beg + j + 1]);
        float2 p2 = __ldg(&g_csr[beg + j + 2]);
        float2 p3 = __ldg(&g_csr[beg + j + 3]);
        __half2 h0 = __ldg(&g_gh[(size_t)__float_as_int(p0.x) * 32 + lane]);
        __half2 h1 = __ldg(&g_gh[(size_t)__float_as_int(p1.x) * 32 + lane]);
        __half2 h2 = __ldg(&g_gh[(size_t)__float_as_int(p2.x) * 32 + lane]);
        __half2 h3 = __ldg(&g_gh[(size_t)__float_as_int(p3.x) * 32 + lane]);
        float2 f0 = __half22float2(h0);
        float2 f1 = __half22float2(h1);
        float2 f2 = __half22float2(h2);
        float2 f3 = __half22float2(h3);
        sum += p0.y + p1.y + p2.y + p3.y;
        ax += p0.y * f0.x + p1.y * f1.x + p2.y * f2.x + p3.y * f3.x;
        ay += p0.y * f0.y + p1.y * f1.y + p2.y * f2.y + p3.y * f3.y;
    }
    for (; j < cnt; j++) {
        float2 p = __ldg(&g_csr[beg + j]);
        float2 f = __half22float2(
            __ldg(&g_gh[(size_t)__float_as_int(p.x) * 32 + lane]));
        sum += p.y;
        ax  += p.y * f.x;
        ay  += p.y * f.y;
    }

    const float inv = 1.0f / sum;
    float2* po = reinterpret_cast<float2*>(out) + (size_t)warp * 32 + lane;
    float2 cur = *po;
    cur.x += ax * inv;
    cur.y += ay * inv;
    *po = cur;
}

// ---------------------------------------------------------------------------
// Launch: fork-join graph — node path (GEMM) overlaps edge path (hist/scan/place)
// ---------------------------------------------------------------------------
extern "C" void kernel_launch(void* const* d_in, const int* in_sizes, int n_in,
                              void* d_out, int out_size) {
    const float* feat = (const float*)d_in[0];
    const float* rel  = (const float*)d_in[1];
    const float* Ws   = (const float*)d_in[2];
    const float* bs   = (const float*)d_in[3];
    const float* Wn   = (const float*)d_in[4];
    const float* bn   = (const float*)d_in[5];
    const float* attn = (const float*)d_in[6];
    const int*   src  = (const int*)d_in[7];
    const int*   dst  = (const int*)d_in[8];
    float* out = (float*)d_out;

    static void*        cnt_addr = nullptr;
    static cudaStream_t s2;
    static cudaEvent_t  evFork, evJoin;
    if (!cnt_addr) {
        cudaFuncSetAttribute(fused_gemm_kernel,
                             cudaFuncAttributeMaxDynamicSharedMemorySize,
                             GEMM_SMEM_BYTES);
        cudaGetSymbolAddress(&cnt_addr, g_cnt);
        cudaStreamCreateWithFlags(&s2, cudaStreamNonBlocking);
        cudaEventCreateWithFlags(&evFork, cudaEventDisableTiming);
        cudaEventCreateWithFlags(&evJoin, cudaEventDisableTiming);
    }

    // Fork: GEMM (node path) on side stream
    cudaEventRecord(evFork, 0);
    cudaStreamWaitEvent(s2, evFork, 0);
    fused_gemm_kernel<<<(N_NODES + 63) / 64, 128, GEMM_SMEM_BYTES, s2>>>(
        feat, Ws, bs, Wn, bn, out);
    cudaEventRecord(evJoin, s2);

    // Edge path on main stream
    cudaMemsetAsync(cnt_addr, 0, N_NODES * sizeof(int));
    hist_kernel <<<(N_EDGES + 255) / 256, 256>>>(dst);
    scan1_kernel<<<NB, SCAN_B>>>();
    scan2_kernel<<<NB, SCAN_B>>>();
    place_kernel<<<(N_EDGES + 255) / 256, 256>>>(rel, attn, src, dst);

    // Join, then aggregate needs both paths
    cudaStreamWaitEvent(0, evJoin, 0);
    aggregate_kernel<<<(N_NODES * 32 + 255) / 256, 256>>>(out);
}